// round 8
// baseline (speedup 1.0000x reference)
#include <cuda_runtime.h>

// LocalAttn, 2-kernel pipeline for GB300 (sm_103a), round 7.
// Kernel A (stage1): thread = pixel; x[32ci] -> registers via 32 coalesced
//   per-channel LDG.32; conv1(fma2) -> fast tanh -> conv2 -> g_mn;
//   v = wv@x (fma2) -> own swizzled smem row -> coalesced STG -> g_v.
//   launch_bounds(256,2): 128 regs, NO spills (the round-5 (256,3) cap spilled).
// Kernel M (combine): gather v halo (coalesced float4, L2-hot), softmax(mask+nb)
//   in registers, combine, write out. (unchanged from round 5)

typedef unsigned long long ull;

__device__ float g_v [2u * 8u * 16384u * 32u];   // [img][g][px][32]  33.5 MB
__device__ float g_mn[2u * 80u * 16384u];        // [img][ch][px]     10.5 MB

__device__ __forceinline__ ull fma2(ull a, ull b, ull c) {
    ull d;
    asm("fma.rn.f32x2 %0, %1, %2, %3;" : "=l"(d) : "l"(a), "l"(b), "l"(c));
    return d;
}
__device__ __forceinline__ float hadd2(ull a) {
    float x, y;
    asm("mov.b64 {%0,%1}, %2;" : "=f"(x), "=f"(y) : "l"(a));
    return x + y;
}
__device__ __forceinline__ ull pk2(float lo, float hi) {
    ull r;
    asm("mov.b64 %0, {%1,%2};" : "=l"(r) : "f"(lo), "f"(hi));
    return r;
}
__device__ __forceinline__ float ftanh(float x) {
    float e = __expf(-2.f * fabsf(x));
    float r = __fdividef(1.f - e, 1.f + e);
    return copysignf(r, x);
}

// ============================ Kernel A ============================
// grid (64, 8, 2) = (px chunk, group, img), block 256, one thread per pixel.
__global__ __launch_bounds__(256, 2)
void stage1_kernel(
    const float* __restrict__ x,
    const float* __restrict__ w1, const float* __restrict__ b1,
    const float* __restrict__ g1, const float* __restrict__ be1,
    const float* __restrict__ m1, const float* __restrict__ v1,
    const float* __restrict__ w2, const float* __restrict__ b2,
    const float* __restrict__ g2, const float* __restrict__ be2,
    const float* __restrict__ m2, const float* __restrict__ v2,
    const float* __restrict__ wv)
{
    __shared__ __align__(16) float s_v9[256 * 36];   // v round-trip (swizzled rows)
    __shared__ __align__(16) float s_w1g[256];       // w1[g]  (8,32)
    __shared__ __align__(16) float s_wvg[1024];      // wv[g]  (32,32)
    __shared__ __align__(16) float s_w2g[80];        // w2[g]  (10,8)
    __shared__ float s_a1[8], s_c1[8], s_a2[10], s_c2[10];

    const int t   = threadIdx.x;
    const int px0 = blockIdx.x * 256;
    const int g   = blockIdx.y;
    const int img = blockIdx.z;

    // weights + folded BN params
    s_w1g[t] = w1[g * 256 + t];
    for (int i = t; i < 1024; i += 256) s_wvg[i] = wv[g * 1024 + i];
    if (t < 80) s_w2g[t] = w2[g * 80 + t];
    if (t < 8) {
        int ch = g * 8 + t;
        float inv = g1[ch] * rsqrtf(v1[ch] + 1e-5f);
        s_a1[t] = inv;
        s_c1[t] = b1[ch] * inv + be1[ch] - m1[ch] * inv;
    } else if (t >= 32 && t < 42) {
        int o = t - 32, ch = g * 10 + o;
        float inv = g2[ch] * rsqrtf(v2[ch] + 1e-5f);
        s_a2[o] = inv;
        s_c2[o] = b2[ch] * inv + be2[ch] - m2[ch] * inv;
    }

    // x -> registers: per channel the warp reads 32 consecutive px (1 line/req)
    const float* xg = x + ((size_t)img * 256 + g * 32) * 16384 + px0 + t;
    float xv[32];
    #pragma unroll
    for (int c = 0; c < 32; c++) xv[c] = __ldg(xg + c * 16384);
    __syncthreads();   // weights visible

    ulonglong2 xr[8];
    #pragma unroll
    for (int q = 0; q < 8; q++) {
        xr[q].x = pk2(xv[4 * q + 0], xv[4 * q + 1]);
        xr[q].y = pk2(xv[4 * q + 2], xv[4 * q + 3]);
    }

    // ---- conv1 -> bn -> tanh -> conv2 -> bn -> g_mn ----
    {
        ull acc[8];
        #pragma unroll
        for (int o = 0; o < 8; o++) acc[o] = 0ULL;
        #pragma unroll
        for (int q = 0; q < 8; q++) {
            #pragma unroll
            for (int o = 0; o < 8; o++) {
                ulonglong2 wp = *(const ulonglong2*)(s_w1g + o * 32 + q * 4);
                acc[o] = fma2(xr[q].x, wp.x, acc[o]);
                acc[o] = fma2(xr[q].y, wp.y, acc[o]);
            }
        }
        float tv[8];
        #pragma unroll
        for (int o = 0; o < 8; o++)
            tv[o] = ftanh(hadd2(acc[o]) * s_a1[o] + s_c1[o]);

        float* mb = g_mn + ((size_t)img * 80 + g * 10) * 16384 + px0 + t;
        #pragma unroll
        for (int o2 = 0; o2 < 10; o2++) {
            float a = 0.f;
            #pragma unroll
            for (int o = 0; o < 8; o++) a += tv[o] * s_w2g[o2 * 8 + o];
            mb[(size_t)o2 * 16384] = a * s_a2[o2] + s_c2[o2];
        }
    }

    // ---- v = wv @ x in 4 chunks of 8 outputs; write own swizzled smem row ----
    const int sw = (t >> 3) & 7;
    float* vrow = s_v9 + t * 36;
    #pragma unroll
    for (int ch = 0; ch < 4; ch++) {
        ull acc[8];
        #pragma unroll
        for (int o = 0; o < 8; o++) acc[o] = 0ULL;
        #pragma unroll
        for (int q = 0; q < 8; q++) {
            #pragma unroll
            for (int o = 0; o < 8; o++) {
                ulonglong2 wp = *(const ulonglong2*)(s_wvg + (ch * 8 + o) * 32 + q * 4);
                acc[o] = fma2(xr[q].x, wp.x, acc[o]);
                acc[o] = fma2(xr[q].y, wp.y, acc[o]);
            }
        }
        float4 r;
        r.x = hadd2(acc[0]); r.y = hadd2(acc[1]);
        r.z = hadd2(acc[2]); r.w = hadd2(acc[3]);
        *(float4*)(vrow + (((2 * ch)     ^ sw) << 2)) = r;
        r.x = hadd2(acc[4]); r.y = hadd2(acc[5]);
        r.z = hadd2(acc[6]); r.w = hadd2(acc[7]);
        *(float4*)(vrow + (((2 * ch + 1) ^ sw) << 2)) = r;
    }
    __syncthreads();

    // ---- coalesced store of v: warp writes 512B contiguous ----
    float* vplane = g_v + ((size_t)(img * 8 + g) * 16384 + px0) * 32;
    #pragma unroll
    for (int i = 0; i < 8; i++) {
        int idx = t + i * 256;          // 2048 float4 items
        int p = idx >> 3, q = idx & 7;
        int sp = (p >> 3) & 7;
        float4 v4 = *(const float4*)(s_v9 + p * 36 + ((q ^ sp) << 2));
        *(float4*)(vplane + p * 32 + q * 4) = v4;
    }
}

// ============================ Kernel M ============================
// grid (8, 8, 16): z = img*8 + g. block 256 (one thread per center pixel).
__global__ __launch_bounds__(256, 4)
void combine_kernel(float* __restrict__ out)
{
    __shared__ __align__(16) float s_v[324 * 36];   // [hp][co] pitch 36

    const int t   = threadIdx.x;
    const int ty  = t >> 4, tx = t & 15;
    const int w0  = blockIdx.x * 16;
    const int h0  = blockIdx.y * 16;
    const int img = blockIdx.z >> 3;
    const int g   = blockIdx.z & 7;
    const int h   = h0 + ty, w = w0 + tx;
    const int px  = h * 128 + w;

    // ---- v halo gather first (overlap L2 latency with scalar work) ----
    const float* vt = g_v + (size_t)(img * 8 + g) * (16384u * 32u);
    #pragma unroll
    for (int i = 0; i < 11; i++) {
        int idx = t + i * 256;
        if (idx < 2592) {
            int hp = idx >> 3, q = idx & 7;
            int hy = hp / 18, hx = hp - hy * 18;
            int hh = h0 + hy - 1, ww = w0 + hx - 1;
            float4 v4 = make_float4(0.f, 0.f, 0.f, 0.f);
            if (((unsigned)hh < 128u) & ((unsigned)ww < 128u))
                v4 = *(const float4*)(vt + (size_t)(hh * 128 + ww) * 32 + q * 4);
            *(float4*)(s_v + hp * 36 + q * 4) = v4;
        }
    }

    // ---- logits: mask (9 strided coalesced) + neighbor (9 predicated) ----
    float a[9];
    {
        const float* nbg   = g_mn + ((size_t)img * 80 + g) * 16384;
        const float* mbase = g_mn + ((size_t)img * 80 + 8 + g * 9) * 16384 + px;
        #pragma unroll
        for (int k = 0; k < 9; k++) {
            int i = k / 3, j = k - i * 3;
            int hh = h + i - 1, ww = w + j - 1;
            float nb = 0.f;
            if (((unsigned)hh < 128u) & ((unsigned)ww < 128u))
                nb = nbg[hh * 128 + ww];
            a[k] = mbase[(size_t)k * 16384] + nb;
        }
        float mx = a[0];
        #pragma unroll
        for (int k = 1; k < 9; k++) mx = fmaxf(mx, a[k]);
        float s = 0.f;
        #pragma unroll
        for (int k = 0; k < 9; k++) { a[k] = __expf(a[k] - mx); s += a[k]; }
        float inv = 1.f / s;
        #pragma unroll
        for (int k = 0; k < 9; k++) a[k] *= inv;
    }
    __syncthreads();

    // ---- combine: out[c] = sum_k a[k] * v[c] at neighbor k ----
    {
        int hpk[9];
        #pragma unroll
        for (int k = 0; k < 9; k++) {
            int i = k / 3, j = k - i * 3;
            hpk[k] = ((ty + i) * 18 + (tx + j)) * 36;
        }
        float* ob = out + ((size_t)img * 256 + g * 32) * 16384 + px;
        #pragma unroll
        for (int c4 = 0; c4 < 8; c4++) {
            float ax = 0.f, ay = 0.f, az = 0.f, aw = 0.f;
            #pragma unroll
            for (int k = 0; k < 9; k++) {
                float4 vv = *(const float4*)(s_v + hpk[k] + c4 * 4);
                ax += a[k] * vv.x; ay += a[k] * vv.y;
                az += a[k] * vv.z; aw += a[k] * vv.w;
            }
            ob[(size_t)(c4 * 4 + 0) * 16384] = ax;
            ob[(size_t)(c4 * 4 + 1) * 16384] = ay;
            ob[(size_t)(c4 * 4 + 2) * 16384] = az;
            ob[(size_t)(c4 * 4 + 3) * 16384] = aw;
        }
    }
}

extern "C" void kernel_launch(void* const* d_in, const int* in_sizes, int n_in,
                              void* d_out, int out_size) {
    const float* x   = (const float*)d_in[0];
    const float* w1  = (const float*)d_in[1];
    const float* b1  = (const float*)d_in[2];
    const float* g1  = (const float*)d_in[3];
    const float* be1 = (const float*)d_in[4];
    const float* m1  = (const float*)d_in[5];
    const float* v1  = (const float*)d_in[6];
    const float* w2  = (const float*)d_in[7];
    const float* b2  = (const float*)d_in[8];
    const float* g2  = (const float*)d_in[9];
    const float* be2 = (const float*)d_in[10];
    const float* m2  = (const float*)d_in[11];
    const float* v2  = (const float*)d_in[12];
    const float* wv  = (const float*)d_in[13];
    float* out = (float*)d_out;

    stage1_kernel<<<dim3(64, 8, 2), 256>>>(x, w1, b1, g1, be1, m1, v1,
                                           w2, b2, g2, be2, m2, v2, wv);
    combine_kernel<<<dim3(8, 8, 16), 256>>>(out);
}

// round 9
// speedup vs baseline: 1.3315x; 1.3315x over previous
#include <cuda_runtime.h>

// LocalAttn, 2-kernel pipeline for GB300 (sm_103a), round 9.
// Kernel MN: thread = pixel; x[32ci] -> regs (coalesced per-channel LDG),
//   conv1(fma2) -> fast tanh -> conv2 -> bn -> g_mn [img][ch][px].
// Kernel F: per (16x16 tile, group, img):
//   warp-cooperative COALESCED staging of the 18x18 x-halo (channel-major
//   row sweeps, ~3 lines/request) into a quad-swizzled smem tile;
//   v = wv@x computed IN PLACE (each halo px's v uses only its own x row);
//   softmax(mask + nb) from g_mn in registers; combine; write out.
//   x is L2-resident (just streamed by MN) -> no g_v DRAM round-trip.

typedef unsigned long long ull;

__device__ float g_mn[2u * 80u * 16384u];        // [img][ch][px]  10.5 MB

__device__ __forceinline__ ull fma2(ull a, ull b, ull c) {
    ull d;
    asm("fma.rn.f32x2 %0, %1, %2, %3;" : "=l"(d) : "l"(a), "l"(b), "l"(c));
    return d;
}
__device__ __forceinline__ float hadd2(ull a) {
    float x, y;
    asm("mov.b64 {%0,%1}, %2;" : "=f"(x), "=f"(y) : "l"(a));
    return x + y;
}
__device__ __forceinline__ ull pk2(float lo, float hi) {
    ull r;
    asm("mov.b64 %0, {%1,%2};" : "=l"(r) : "f"(lo), "f"(hi));
    return r;
}
__device__ __forceinline__ float ftanh(float x) {
    float e = __expf(-2.f * fabsf(x));
    float r = __fdividef(1.f - e, 1.f + e);
    return copysignf(r, x);
}

// ============================ Kernel MN ============================
// grid (64, 8, 2) = (px chunk, conv group, img), block 256, thread = pixel.
__global__ __launch_bounds__(256)
void mn_kernel(
    const float* __restrict__ x,
    const float* __restrict__ w1, const float* __restrict__ b1,
    const float* __restrict__ g1, const float* __restrict__ be1,
    const float* __restrict__ m1, const float* __restrict__ v1,
    const float* __restrict__ w2, const float* __restrict__ b2,
    const float* __restrict__ g2, const float* __restrict__ be2,
    const float* __restrict__ m2, const float* __restrict__ v2)
{
    __shared__ __align__(16) float s_w1g[256];       // w1[g] (8,32)
    __shared__ __align__(16) float s_w2g[80];        // w2[g] (10,8)
    __shared__ float s_a1[8], s_c1[8], s_a2[10], s_c2[10];

    const int t   = threadIdx.x;
    const int px0 = blockIdx.x * 256;
    const int g   = blockIdx.y;
    const int img = blockIdx.z;

    s_w1g[t] = w1[g * 256 + t];
    if (t < 80) s_w2g[t] = w2[g * 80 + t];
    if (t < 8) {
        int ch = g * 8 + t;
        float inv = g1[ch] * rsqrtf(v1[ch] + 1e-5f);
        s_a1[t] = inv;
        s_c1[t] = b1[ch] * inv + be1[ch] - m1[ch] * inv;
    } else if (t >= 32 && t < 42) {
        int o = t - 32, ch = g * 10 + o;
        float inv = g2[ch] * rsqrtf(v2[ch] + 1e-5f);
        s_a2[o] = inv;
        s_c2[o] = b2[ch] * inv + be2[ch] - m2[ch] * inv;
    }

    const float* xg = x + ((size_t)img * 256 + g * 32) * 16384 + px0 + t;
    float xv[32];
    #pragma unroll
    for (int c = 0; c < 32; c++) xv[c] = __ldg(xg + c * 16384);
    __syncthreads();

    ulonglong2 xr[8];
    #pragma unroll
    for (int q = 0; q < 8; q++) {
        xr[q].x = pk2(xv[4 * q + 0], xv[4 * q + 1]);
        xr[q].y = pk2(xv[4 * q + 2], xv[4 * q + 3]);
    }

    ull acc[8];
    #pragma unroll
    for (int o = 0; o < 8; o++) acc[o] = 0ULL;
    #pragma unroll
    for (int q = 0; q < 8; q++) {
        #pragma unroll
        for (int o = 0; o < 8; o++) {
            ulonglong2 wp = *(const ulonglong2*)(s_w1g + o * 32 + q * 4);
            acc[o] = fma2(xr[q].x, wp.x, acc[o]);
            acc[o] = fma2(xr[q].y, wp.y, acc[o]);
        }
    }
    float tv[8];
    #pragma unroll
    for (int o = 0; o < 8; o++)
        tv[o] = ftanh(hadd2(acc[o]) * s_a1[o] + s_c1[o]);

    float* mb = g_mn + ((size_t)img * 80 + g * 10) * 16384 + px0 + t;
    #pragma unroll
    for (int o2 = 0; o2 < 10; o2++) {
        float a = 0.f;
        #pragma unroll
        for (int o = 0; o < 8; o++) a += tv[o] * s_w2g[o2 * 8 + o];
        mb[(size_t)o2 * 16384] = a * s_a2[o2] + s_c2[o2];
    }
}

// ============================ Kernel F ============================
// grid (8, 8, 16): z = img*8 + g. block 256 (one thread per center pixel).
// dynamic smem: s_xv[324*36] + s_wv[1024] = 50752 B.
// s_xv layout: word = hp*36 + ((q ^ ((hp>>3)&7))<<2) + w  (channel c = 4q + w)
__global__ __launch_bounds__(256, 2)
void fused_kernel(const float* __restrict__ x,
                  const float* __restrict__ wv,
                  float* __restrict__ out)
{
    extern __shared__ __align__(16) float sm[];
    float* s_xv = sm;            // x halo, later v (in place)
    float* s_wv = sm + 11664;    // wv[g] (32,32)

    const int t    = threadIdx.x;
    const int lane = t & 31;
    const int wq   = t >> 5;
    const int ty   = t >> 4, tx = t & 15;
    const int w0   = blockIdx.x * 16;
    const int h0   = blockIdx.y * 16;
    const int img  = blockIdx.z >> 3;
    const int g    = blockIdx.z & 7;
    const int h    = h0 + ty, w = w0 + tx;
    const int px   = h * 128 + w;

    for (int i = t; i < 1024; i += 256) s_wv[i] = wv[g * 1024 + i];

    // ---- coalesced x-halo staging: warp wq loads channels 4wq..4wq+3 ----
    {
        const float* xg = x + ((size_t)img * 256 + g * 32) * 16384;
        #pragma unroll
        for (int rep = 0; rep < 4; rep++) {
            int c = wq * 4 + rep;
            int qc = c >> 2, wc = c & 3;
            const float* src = xg + (size_t)c * 16384;
            #pragma unroll
            for (int i = 0; i < 11; i++) {
                int idx = lane + i * 32;
                if (idx < 324) {
                    int hy = idx / 18, hx = idx - hy * 18;
                    int hh = h0 + hy - 1, ww = w0 + hx - 1;
                    float v = 0.f;
                    if (((unsigned)hh < 128u) & ((unsigned)ww < 128u))
                        v = __ldg(src + hh * 128 + ww);
                    s_xv[idx * 36 + (((qc ^ ((idx >> 3) & 7)) << 2) + wc)] = v;
                }
            }
        }
    }

    // ---- logits + softmax (global reads only; overlaps staging latency) ----
    float a[9];
    {
        const float* nbg   = g_mn + ((size_t)img * 80 + g) * 16384;
        const float* mbase = g_mn + ((size_t)img * 80 + 8 + g * 9) * 16384 + px;
        #pragma unroll
        for (int k = 0; k < 9; k++) {
            int i = k / 3, j = k - i * 3;
            int hh = h + i - 1, ww = w + j - 1;
            float nb = 0.f;
            if (((unsigned)hh < 128u) & ((unsigned)ww < 128u))
                nb = nbg[hh * 128 + ww];
            a[k] = mbase[(size_t)k * 16384] + nb;
        }
        float mx = a[0];
        #pragma unroll
        for (int k = 1; k < 9; k++) mx = fmaxf(mx, a[k]);
        float s = 0.f;
        #pragma unroll
        for (int k = 0; k < 9; k++) { a[k] = __expf(a[k] - mx); s += a[k]; }
        float inv = 1.f / s;
        #pragma unroll
        for (int k = 0; k < 9; k++) a[k] *= inv;
    }
    __syncthreads();

    // ---- v = wv @ x per halo pixel, IN PLACE (own row only) ----
    for (int hp = t; hp < 324; hp += 256) {
        const int sw = (hp >> 3) & 7;
        float* row = s_xv + hp * 36;

        ulonglong2 xr[8];
        #pragma unroll
        for (int q = 0; q < 8; q++)
            xr[q] = *(const ulonglong2*)(row + ((q ^ sw) << 2));

        #pragma unroll
        for (int ch = 0; ch < 4; ch++) {
            ull acc[8];
            #pragma unroll
            for (int o = 0; o < 8; o++) acc[o] = 0ULL;
            #pragma unroll
            for (int q = 0; q < 8; q++) {
                #pragma unroll
                for (int o = 0; o < 8; o++) {
                    ulonglong2 wp = *(const ulonglong2*)(s_wv + (ch * 8 + o) * 32 + q * 4);
                    acc[o] = fma2(xr[q].x, wp.x, acc[o]);
                    acc[o] = fma2(xr[q].y, wp.y, acc[o]);
                }
            }
            float4 r;
            r.x = hadd2(acc[0]); r.y = hadd2(acc[1]);
            r.z = hadd2(acc[2]); r.w = hadd2(acc[3]);
            *(float4*)(row + (((2 * ch)     ^ sw) << 2)) = r;
            r.x = hadd2(acc[4]); r.y = hadd2(acc[5]);
            r.z = hadd2(acc[6]); r.w = hadd2(acc[7]);
            *(float4*)(row + (((2 * ch + 1) ^ sw) << 2)) = r;
        }
    }
    __syncthreads();

    // ---- combine: out[c] = sum_k a[k] * v[c] at neighbor k ----
    {
        int hpk[9], swk[9];
        #pragma unroll
        for (int k = 0; k < 9; k++) {
            int i = k / 3, j = k - i * 3;
            int hp = (ty + i) * 18 + (tx + j);
            hpk[k] = hp * 36;
            swk[k] = (hp >> 3) & 7;
        }
        float* ob = out + ((size_t)img * 256 + g * 32) * 16384 + px;
        #pragma unroll
        for (int c4 = 0; c4 < 8; c4++) {
            float ax = 0.f, ay = 0.f, az = 0.f, aw = 0.f;
            #pragma unroll
            for (int k = 0; k < 9; k++) {
                float4 vv = *(const float4*)(s_xv + hpk[k] + (((c4 ^ swk[k])) << 2));
                ax += a[k] * vv.x; ay += a[k] * vv.y;
                az += a[k] * vv.z; aw += a[k] * vv.w;
            }
            ob[(size_t)(c4 * 4 + 0) * 16384] = ax;
            ob[(size_t)(c4 * 4 + 1) * 16384] = ay;
            ob[(size_t)(c4 * 4 + 2) * 16384] = az;
            ob[(size_t)(c4 * 4 + 3) * 16384] = aw;
        }
    }
}

static const int F_SMEM = (11664 + 1024) * 4;   // 50752 B

extern "C" void kernel_launch(void* const* d_in, const int* in_sizes, int n_in,
                              void* d_out, int out_size) {
    const float* x   = (const float*)d_in[0];
    const float* w1  = (const float*)d_in[1];
    const float* b1  = (const float*)d_in[2];
    const float* g1  = (const float*)d_in[3];
    const float* be1 = (const float*)d_in[4];
    const float* m1  = (const float*)d_in[5];
    const float* v1  = (const float*)d_in[6];
    const float* w2  = (const float*)d_in[7];
    const float* b2  = (const float*)d_in[8];
    const float* g2  = (const float*)d_in[9];
    const float* be2 = (const float*)d_in[10];
    const float* m2  = (const float*)d_in[11];
    const float* v2  = (const float*)d_in[12];
    const float* wv  = (const float*)d_in[13];
    float* out = (float*)d_out;

    static int inited = 0;
    if (!inited) {
        cudaFuncSetAttribute(fused_kernel,
                             cudaFuncAttributeMaxDynamicSharedMemorySize, F_SMEM);
        inited = 1;
    }

    mn_kernel<<<dim3(64, 8, 2), 256>>>(x, w1, b1, g1, be1, m1, v1,
                                       w2, b2, g2, be2, m2, v2);
    fused_kernel<<<dim3(8, 8, 16), 256, F_SMEM>>>(x, wv, out);
}